// round 1
// baseline (speedup 1.0000x reference)
#include <cuda_runtime.h>
#include <cuda_bf16.h>

#define N_NODES 20000
#define M_EDGES 5000
#define DIN 256
#define DOUTD 512
#define DCAT 1024

// -------- scratch (static device globals; allocation-free) --------
__device__ float g_xpr[(size_t)N_NODES * DCAT];    // [N,1024]: cols 0:512 x@W_node, 512:1024 x@W_res
__device__ float g_edge[(size_t)M_EDGES * DOUTD];  // [M,512]
__device__ float g_hbuf[(size_t)N_NODES * DOUTD];  // [N,512] pre-LN
__device__ float g_inv_dv[N_NODES];
__device__ float g_de_sum[M_EDGES];
__device__ float g_inv_de[M_EDGES];

// =====================================================================
// GEMM1: C[n, j] = sum_k x[n,k] * Wcat[k,j],  Wcat = [W_node | W_res]
// BM=128, BN=64, BK=16, 256 threads, per-thread 8x4
// =====================================================================
__global__ __launch_bounds__(256) void gemm_xw_kernel(
    const float* __restrict__ x, const float* __restrict__ Wn,
    const float* __restrict__ Wr)
{
    __shared__ float As[16][128 + 4];
    __shared__ float Bs[16][64];
    const int bm = blockIdx.x * 128;
    const int bn = blockIdx.y * 64;
    const int t = threadIdx.x;
    const int trow = t / 16, tcol = t % 16;
    float acc[8][4] = {};

    for (int k0 = 0; k0 < DIN; k0 += 16) {
        // A tile: 128x16 (2 float4 per thread), transpose into As[k][m]
#pragma unroll
        for (int i = 0; i < 2; i++) {
            int idx = t + i * 256;
            int r = idx / 4, c4 = idx % 4;
            int gr = bm + r;
            float4 v = make_float4(0.f, 0.f, 0.f, 0.f);
            if (gr < N_NODES) v = *(const float4*)&x[(size_t)gr * DIN + k0 + c4 * 4];
            As[c4 * 4 + 0][r] = v.x;
            As[c4 * 4 + 1][r] = v.y;
            As[c4 * 4 + 2][r] = v.z;
            As[c4 * 4 + 3][r] = v.w;
        }
        // B tile: 16x64 (1 float4 per thread)
        {
            int r = t / 16, c4 = t % 16;
            int gk = k0 + r;
            int gj = bn + c4 * 4;
            const float* src = (gj < DOUTD) ? (Wn + (size_t)gk * DOUTD + gj)
                                            : (Wr + (size_t)gk * DOUTD + (gj - DOUTD));
            *(float4*)&Bs[r][c4 * 4] = *(const float4*)src;
        }
        __syncthreads();
#pragma unroll
        for (int kk = 0; kk < 16; kk++) {
            float a[8], b[4];
#pragma unroll
            for (int i = 0; i < 8; i++) a[i] = As[kk][trow * 8 + i];
#pragma unroll
            for (int j = 0; j < 4; j++) b[j] = Bs[kk][tcol * 4 + j];
#pragma unroll
            for (int i = 0; i < 8; i++)
#pragma unroll
                for (int j = 0; j < 4; j++) acc[i][j] += a[i] * b[j];
        }
        __syncthreads();
    }
#pragma unroll
    for (int i = 0; i < 8; i++) {
        int gr = bm + trow * 8 + i;
        if (gr >= N_NODES) continue;
#pragma unroll
        for (int j = 0; j < 4; j++)
            g_xpr[(size_t)gr * DCAT + bn + tcol * 4 + j] = acc[i][j];
    }
}

// =====================================================================
// degree kernels
// =====================================================================
__global__ void dv_kernel(const float* __restrict__ H)
{
    int warp = (blockIdx.x * blockDim.x + threadIdx.x) >> 5;
    int lane = threadIdx.x & 31;
    if (warp >= N_NODES) return;
    const float4* row = (const float4*)(H + (size_t)warp * M_EDGES);
    float s = 0.f;
    for (int c = lane; c < M_EDGES / 4; c += 32) {
        float4 v = row[c];
        s += v.x + v.y + v.z + v.w;
    }
#pragma unroll
    for (int o = 16; o > 0; o >>= 1) s += __shfl_xor_sync(0xffffffffu, s, o);
    if (lane == 0) g_inv_dv[warp] = 1.0f / fmaxf(s, 1.0f);
}

__global__ void zero_de_kernel()
{
    int i = blockIdx.x * blockDim.x + threadIdx.x;
    if (i < M_EDGES) g_de_sum[i] = 0.f;
}

// grid (20, 40): 256 columns per block.x, 500 rows per block.y
__global__ void de_partial_kernel(const float* __restrict__ H)
{
    int m = blockIdx.x * 256 + threadIdx.x;
    if (m >= M_EDGES) return;
    int r0 = blockIdx.y * 500;
    float s = 0.f;
#pragma unroll 4
    for (int n = r0; n < r0 + 500; n += 4) {
        float a0 = H[(size_t)(n + 0) * M_EDGES + m];
        float a1 = H[(size_t)(n + 1) * M_EDGES + m];
        float a2 = H[(size_t)(n + 2) * M_EDGES + m];
        float a3 = H[(size_t)(n + 3) * M_EDGES + m];
        s += (a0 + a1) + (a2 + a3);
    }
    atomicAdd(&g_de_sum[m], s);  // sums of exact 0/1 integers -> deterministic
}

__global__ void de_fin_kernel()
{
    int m = blockIdx.x * blockDim.x + threadIdx.x;
    if (m < M_EDGES) g_inv_de[m] = 1.0f / fmaxf(g_de_sum[m], 1.0f);
}

// =====================================================================
// GEMM2: edge_feat[m,j] = inv_de[m] * sum_n H[n,m] * xpr[n,j]
// A[m,k] = H[k*M+m] (natural k-major tiles, no transpose needed)
// BM=64 (m), BN=128 (j), BK=16 (n), 256 threads, per-thread 4x8
// =====================================================================
__global__ __launch_bounds__(256) void gemm_edge_kernel(const float* __restrict__ H)
{
    __shared__ float As[16][64];
    __shared__ float Bs[16][128];
    const int bm = blockIdx.x * 64;
    const int bn = blockIdx.y * 128;
    const int t = threadIdx.x;
    const int trow = t / 16, tcol = t % 16;
    float acc[4][8] = {};

    for (int k0 = 0; k0 < N_NODES; k0 += 16) {
        // A tile: 16 rows(k) x 64 cols(m), 1 float4/thread
        {
            int kk = t / 16, m4 = t % 16;
            int gm = bm + m4 * 4;
            float4 v = make_float4(0.f, 0.f, 0.f, 0.f);
            if (gm < M_EDGES) v = *(const float4*)&H[(size_t)(k0 + kk) * M_EDGES + gm];
            *(float4*)&As[kk][m4 * 4] = v;
        }
        // B tile: 16 x 128 from g_xpr (cols 0:512), 2 float4/thread
#pragma unroll
        for (int i = 0; i < 2; i++) {
            int idx = t + i * 256;
            int kk = idx / 32, c4 = idx % 32;
            *(float4*)&Bs[kk][c4 * 4] =
                *(const float4*)&g_xpr[(size_t)(k0 + kk) * DCAT + bn + c4 * 4];
        }
        __syncthreads();
#pragma unroll
        for (int kk = 0; kk < 16; kk++) {
            float a[4], b[8];
#pragma unroll
            for (int i = 0; i < 4; i++) a[i] = As[kk][trow * 4 + i];
#pragma unroll
            for (int j = 0; j < 8; j++) b[j] = Bs[kk][tcol * 8 + j];
#pragma unroll
            for (int i = 0; i < 4; i++)
#pragma unroll
                for (int j = 0; j < 8; j++) acc[i][j] += a[i] * b[j];
        }
        __syncthreads();
    }
#pragma unroll
    for (int i = 0; i < 4; i++) {
        int gm = bm + trow * 4 + i;
        if (gm >= M_EDGES) continue;
        float s = g_inv_de[gm];
#pragma unroll
        for (int j = 0; j < 8; j++)
            g_edge[(size_t)gm * DOUTD + bn + tcol * 8 + j] = acc[i][j] * s;
    }
}

// =====================================================================
// GEMM3: h[n,j] = inv_dv[n] * sum_m H[n,m]*edge[m,j] + xpr[n, 512+j]
// BM=128 (n), BN=128 (j), BK=8 (m), 256 threads, per-thread 8x8
// =====================================================================
__global__ __launch_bounds__(256) void gemm_node_kernel(const float* __restrict__ H)
{
    __shared__ float As[8][128 + 4];
    __shared__ float Bs[8][128];
    const int bm = blockIdx.x * 128;  // n
    const int bn = blockIdx.y * 128;  // j
    const int t = threadIdx.x;
    const int trow = t / 16, tcol = t % 16;
    float acc[8][8] = {};

    for (int k0 = 0; k0 < M_EDGES; k0 += 8) {
        // A tile: 128x8 of H, 1 float4/thread, transpose into As[k][n]
        {
            int r = t / 2, c4 = t % 2;
            int gn = bm + r;
            float4 v = make_float4(0.f, 0.f, 0.f, 0.f);
            if (gn < N_NODES) v = *(const float4*)&H[(size_t)gn * M_EDGES + k0 + c4 * 4];
            As[c4 * 4 + 0][r] = v.x;
            As[c4 * 4 + 1][r] = v.y;
            As[c4 * 4 + 2][r] = v.z;
            As[c4 * 4 + 3][r] = v.w;
        }
        // B tile: 8x128 from g_edge, 1 float4/thread
        {
            int kk = t / 32, c4 = t % 32;
            *(float4*)&Bs[kk][c4 * 4] =
                *(const float4*)&g_edge[(size_t)(k0 + kk) * DOUTD + bn + c4 * 4];
        }
        __syncthreads();
#pragma unroll
        for (int kk = 0; kk < 8; kk++) {
            float a[8], b[8];
#pragma unroll
            for (int i = 0; i < 8; i++) a[i] = As[kk][trow * 8 + i];
#pragma unroll
            for (int j = 0; j < 8; j++) b[j] = Bs[kk][tcol * 8 + j];
#pragma unroll
            for (int i = 0; i < 8; i++)
#pragma unroll
                for (int j = 0; j < 8; j++) acc[i][j] += a[i] * b[j];
        }
        __syncthreads();
    }
#pragma unroll
    for (int i = 0; i < 8; i++) {
        int gn = bm + trow * 8 + i;
        if (gn >= N_NODES) continue;
        float s = g_inv_dv[gn];
#pragma unroll
        for (int j = 0; j < 8; j++) {
            int gj = bn + tcol * 8 + j;
            g_hbuf[(size_t)gn * DOUTD + gj] =
                acc[i][j] * s + g_xpr[(size_t)gn * DCAT + DOUTD + gj];
        }
    }
}

// =====================================================================
// LayerNorm: block (256 threads) per row of 512
// =====================================================================
__device__ __forceinline__ float block_sum_256(float v, float* red)
{
#pragma unroll
    for (int o = 16; o > 0; o >>= 1) v += __shfl_xor_sync(0xffffffffu, v, o);
    int w = threadIdx.x >> 5;
    if ((threadIdx.x & 31) == 0) red[w] = v;
    __syncthreads();
    if (threadIdx.x < 32) {
        float r = (threadIdx.x < 8) ? red[threadIdx.x] : 0.0f;
#pragma unroll
        for (int o = 4; o > 0; o >>= 1) r += __shfl_xor_sync(0xffffffffu, r, o);
        if (threadIdx.x == 0) red[0] = r;
    }
    __syncthreads();
    float res = red[0];
    __syncthreads();
    return res;
}

__global__ __launch_bounds__(256) void ln_kernel(
    const float* __restrict__ gamma, const float* __restrict__ beta,
    float* __restrict__ out)
{
    __shared__ float red[8];
    const int row = blockIdx.x;
    const int t = threadIdx.x;
    const float* h = g_hbuf + (size_t)row * DOUTD;
    float2 v = *(const float2*)&h[t * 2];
    float mu = block_sum_256(v.x + v.y, red) * (1.0f / DOUTD);
    float dx = v.x - mu, dy = v.y - mu;
    float var = block_sum_256(dx * dx + dy * dy, red) * (1.0f / DOUTD);
    float rs = rsqrtf(var + 1e-5f);
    float2 g = *(const float2*)&gamma[t * 2];
    float2 b = *(const float2*)&beta[t * 2];
    float* o = out + (size_t)row * DOUTD;
    o[t * 2 + 0] = dx * rs * g.x + b.x;
    o[t * 2 + 1] = dy * rs * g.y + b.y;
}

// =====================================================================
// launch
// =====================================================================
extern "C" void kernel_launch(void* const* d_in, const int* in_sizes, int n_in,
                              void* d_out, int out_size)
{
    const float* x     = (const float*)d_in[0];  // [20000,256]
    const float* H     = (const float*)d_in[1];  // [20000,5000]
    const float* Wn    = (const float*)d_in[2];  // [256,512]
    const float* Wr    = (const float*)d_in[3];  // [256,512]
    const float* gamma = (const float*)d_in[4];  // [512]
    const float* beta  = (const float*)d_in[5];  // [512]
    float* out = (float*)d_out;                  // [20000,512]

    // projections: x @ [W_node | W_res]
    gemm_xw_kernel<<<dim3(157, 16), 256>>>(x, Wn, Wr);

    // degrees
    zero_de_kernel<<<20, 256>>>();
    dv_kernel<<<2500, 256>>>(H);                 // 20000 warps
    de_partial_kernel<<<dim3(20, 40), 256>>>(H);
    de_fin_kernel<<<20, 256>>>();

    // edge aggregation: (H^T @ x_proj) / d_e
    gemm_edge_kernel<<<dim3(79, 4), 256>>>(H);

    // node update + residual: (H @ edge_feat)/d_v + x@W_res
    gemm_node_kernel<<<dim3(157, 4), 256>>>(H);

    // LayerNorm
    ln_kernel<<<N_NODES, 256>>>(gamma, beta, out);
}

// round 4
// speedup vs baseline: 2.9073x; 2.9073x over previous
#include <cuda_runtime.h>
#include <cuda_bf16.h>
#include <cstdint>

#define N_NODES 20000
#define M_EDGES 5000
#define DIN 256
#define DOUTD 512

// padded dims
#define NP_M 20096            // N padded to 157*128 (MMA M tiles)
#define NP_K 20032            // N padded to 313*64 (K multiples of 64/32)
#define MP_M 5120             // M padded to 40*128
#define MP_K 5056             // M padded to 79*64

// -------- scratch (__device__ globals are zero-initialized; pad regions are
// never written, so padding stays zero across all launches) --------
__device__ __nv_bfloat16 g_Axx[(size_t)NP_M * 1024];     // [n, 1024] = [xh|xl|xh|xl]
__device__ __nv_bfloat16 g_Bww[(size_t)1024 * 1024];     // [jcat, 1024] = [wh|wl|wl|wh]
__device__ float         g_xpr[(size_t)NP_M * 1024];     // [n, 1024]: 0:512 x@Wn, 512:1024 x@Wr
__device__ __nv_bfloat16 g_xprT[(size_t)1024 * NP_K];    // [jcat, n]: rows 0:512 hi, 512:1024 lo
__device__ __nv_bfloat16 g_Hbf[(size_t)NP_M * MP_K];     // [n, m] bf16
__device__ __nv_bfloat16 g_Ht[(size_t)MP_M * NP_K];      // [m, n] bf16 (transpose)
__device__ __nv_bfloat16 g_ET[(size_t)1024 * MP_K];      // [jcat, m]: rows 0:512 hi, 512:1024 lo
__device__ float         g_D2[(size_t)MP_M * 1024];      // [m, jcat]
__device__ float         g_D3[(size_t)NP_M * 1024];      // [n, jcat]
__device__ float         g_dv_sum[N_NODES];
__device__ float         g_de_sum[MP_M];
__device__ float         g_inv_dv[N_NODES];
__device__ float         g_inv_de[MP_M];

// ============================ helpers ============================
__device__ __forceinline__ uint32_t smem_u32(const void* p) {
    uint32_t a;
    asm("{ .reg .u64 t; cvta.to.shared.u64 t, %1; cvt.u32.u64 %0, t; }" : "=r"(a) : "l"(p));
    return a;
}
__device__ __forceinline__ void cp16(uint32_t dst, const void* src) {
    asm volatile("cp.async.cg.shared.global [%0], [%1], 16;" :: "r"(dst), "l"(src));
}
#define CP_COMMIT() asm volatile("cp.async.commit_group;" ::: "memory")
#define CP_WAIT(n)  asm volatile("cp.async.wait_group %0;" :: "n"(n) : "memory")

__device__ __forceinline__ void ldsm4(uint32_t* r, uint32_t addr) {
    asm volatile("ldmatrix.sync.aligned.m8n8.x4.shared.b16 {%0,%1,%2,%3}, [%4];"
        : "=r"(r[0]), "=r"(r[1]), "=r"(r[2]), "=r"(r[3]) : "r"(addr));
}
__device__ __forceinline__ void mma16816(float* c, const uint32_t* a,
                                         uint32_t b0, uint32_t b1) {
    asm volatile(
        "mma.sync.aligned.m16n8k16.row.col.f32.bf16.bf16.f32 "
        "{%0,%1,%2,%3}, {%4,%5,%6,%7}, {%8,%9}, {%0,%1,%2,%3};"
        : "+f"(c[0]), "+f"(c[1]), "+f"(c[2]), "+f"(c[3])
        : "r"(a[0]), "r"(a[1]), "r"(a[2]), "r"(a[3]), "r"(b0), "r"(b1));
}

// ============================ MMA GEMM =============================
// D[row0:row0+128, col0:col0+256] = A[rows,K] @ B[cols,K]^T
// A,B: K-major bf16, row stride ldab (elements). D fp32 row-major, ld=1024.
// BM=128, BN=256, BK=32, 256 threads (8 warps, 2m x 4n), 3-stage cp.async.
#define STAGES 3
#define ST_A 10240            // 128 rows * 80B
#define ST_B 20480            // 256 rows * 80B
#define ST_SZ (ST_A + ST_B)   // 30720
#define SMEM_MMA (ST_SZ * STAGES)

__global__ __launch_bounds__(256) void mma_kernel(
    const __nv_bfloat16* __restrict__ A, const __nv_bfloat16* __restrict__ B,
    float* __restrict__ D, int ldab, int niter)
{
    extern __shared__ char dynsmem[];
    const uint32_t sb = smem_u32(dynsmem);
    const int tid = threadIdx.x;
    const int lane = tid & 31, wid = tid >> 5;
    const int wm = wid & 1, wn = wid >> 1;       // warp grid 2 x 4
    const int row0 = blockIdx.x * 128;
    const int col0 = blockIdx.y * 256;

    const __nv_bfloat16* Ab = A + (size_t)row0 * ldab;
    const __nv_bfloat16* Bb = B + (size_t)col0 * ldab;

    // per-thread ldmatrix lane addressing
    const int ra = (lane & 7) + ((lane >> 3) & 1) * 8;  // A row add
    const int ka = (lane >> 4) * 8;                     // A k add
    const int rb = (lane & 7) + (lane >> 4) * 8;        // B row add
    const int kb = ((lane >> 3) & 1) * 8;               // B k add

    // load-index precompute
    const int lrA = tid >> 2, lcA = tid & 3;            // + i*64 rows

    float acc[4][8][4];
#pragma unroll
    for (int i = 0; i < 4; i++)
#pragma unroll
        for (int j = 0; j < 8; j++)
#pragma unroll
            for (int k = 0; k < 4; k++) acc[i][j][k] = 0.f;

    auto issue_load = [&](int buf, int chunk) {
        const uint32_t sa = sb + buf * ST_SZ;
        const uint32_t sB = sa + ST_A;
        const __nv_bfloat16* Ak = Ab + chunk * 32;
        const __nv_bfloat16* Bk = Bb + chunk * 32;
#pragma unroll
        for (int i = 0; i < 2; i++) {
            int r = lrA + i * 64;
            cp16(sa + r * 80 + lcA * 16, Ak + (size_t)r * ldab + lcA * 8);
        }
#pragma unroll
        for (int i = 0; i < 4; i++) {
            int r = lrA + i * 64;
            cp16(sB + r * 80 + lcA * 16, Bk + (size_t)r * ldab + lcA * 8);
        }
    };

    // prologue
    issue_load(0, 0); CP_COMMIT();
    if (niter > 1) issue_load(1, 1);
    CP_COMMIT();

    for (int it = 0; it < niter; it++) {
        CP_WAIT(1);
        __syncthreads();
        const int buf = it % STAGES;
        const uint32_t sa = sb + buf * ST_SZ;
        const uint32_t sB = sa + ST_A;
#pragma unroll
        for (int ks = 0; ks < 2; ks++) {
            uint32_t afr[4][4], bfr[4][4];
#pragma unroll
            for (int mb = 0; mb < 4; mb++)
                ldsm4(afr[mb], sa + (wm * 64 + mb * 16 + ra) * 80 + (ks * 16 + ka) * 2);
#pragma unroll
            for (int np = 0; np < 4; np++)
                ldsm4(bfr[np], sB + (wn * 64 + np * 16 + rb) * 80 + (ks * 16 + kb) * 2);
#pragma unroll
            for (int mb = 0; mb < 4; mb++)
#pragma unroll
                for (int np = 0; np < 4; np++) {
                    mma16816(acc[mb][np * 2], afr[mb], bfr[np][0], bfr[np][1]);
                    mma16816(acc[mb][np * 2 + 1], afr[mb], bfr[np][2], bfr[np][3]);
                }
        }
        __syncthreads();
        if (it + 2 < niter) issue_load((it + 2) % STAGES, it + 2);
        CP_COMMIT();
    }

    // epilogue: direct fp32 stores
    const int rbase = row0 + wm * 64 + (lane >> 2);
    const int cbase = col0 + wn * 64 + (lane & 3) * 2;
#pragma unroll
    for (int mb = 0; mb < 4; mb++) {
#pragma unroll
        for (int nb = 0; nb < 8; nb++) {
            const int r = rbase + mb * 16;
            const int c = cbase + nb * 8;
            *(float2*)&D[(size_t)r * 1024 + c] = make_float2(acc[mb][nb][0], acc[mb][nb][1]);
            *(float2*)&D[(size_t)(r + 8) * 1024 + c] = make_float2(acc[mb][nb][2], acc[mb][nb][3]);
        }
    }
}

// ===================== conversion / epilogue kernels =====================
__global__ void zero_sums_kernel()
{
    int i = blockIdx.x * blockDim.x + threadIdx.x;
    if (i < N_NODES) g_dv_sum[i] = 0.f;
    if (i < MP_M) g_de_sum[i] = 0.f;
}

// H -> H_bf [n,m], Ht [m,n] (bf16), plus degree partial sums. 32x32 tiles.
__global__ __launch_bounds__(256) void convH_kernel(const float* __restrict__ H)
{
    __shared__ float tile[32][33];
    __shared__ float colpart[8][32];
    const int tx = threadIdx.x, ty = threadIdx.y;
    const int m0 = blockIdx.x * 32, n0 = blockIdx.y * 32;
    const int m = m0 + tx;
    float v[4];
#pragma unroll
    for (int r = 0; r < 4; r++) {
        int n = n0 + ty * 4 + r;
        float val = (m < M_EDGES) ? H[(size_t)n * M_EDGES + m] : 0.f;
        v[r] = val;
        tile[ty * 4 + r][tx] = val;
        if (m < M_EDGES)
            g_Hbf[(size_t)n * MP_K + m] = __float2bfloat16(val);
    }
#pragma unroll
    for (int r = 0; r < 4; r++) {
        float s = v[r];
#pragma unroll
        for (int o = 16; o > 0; o >>= 1) s += __shfl_xor_sync(0xffffffffu, s, o);
        if (tx == 0) atomicAdd(&g_dv_sum[n0 + ty * 4 + r], s);
    }
    colpart[ty][tx] = v[0] + v[1] + v[2] + v[3];
    __syncthreads();
    if (ty == 0 && m < M_EDGES) {
        float s = 0.f;
#pragma unroll
        for (int w = 0; w < 8; w++) s += colpart[w][tx];
        atomicAdd(&g_de_sum[m], s);
    }
#pragma unroll
    for (int r = 0; r < 4; r++) {
        int ml = ty * 4 + r;
        if (m0 + ml < M_EDGES)
            g_Ht[(size_t)(m0 + ml) * NP_K + n0 + tx] = __float2bfloat16(tile[tx][ml]);
    }
}

__global__ void deg_fin_kernel()
{
    int i = blockIdx.x * blockDim.x + threadIdx.x;
    if (i < N_NODES) g_inv_dv[i] = 1.0f / fmaxf(g_dv_sum[i], 1.0f);
    if (i < M_EDGES) g_inv_de[i] = 1.0f / fmaxf(g_de_sum[i], 1.0f);
}

// x [n,256] -> Axx [n,1024] = [xh | xl | xh | xl]
__global__ __launch_bounds__(256) void convX_kernel(const float* __restrict__ x)
{
    const int n = blockIdx.x, k = threadIdx.x;
    float v = x[(size_t)n * DIN + k];
    __nv_bfloat16 hi = __float2bfloat16(v);
    __nv_bfloat16 lo = __float2bfloat16(v - __bfloat162float(hi));
    __nv_bfloat16* row = g_Axx + (size_t)n * 1024;
    row[k] = hi; row[256 + k] = lo; row[512 + k] = hi; row[768 + k] = lo;
}

// Wn,Wr [256,512] -> Bww [jcat,1024] = [wh | wl | wl | wh]
__global__ __launch_bounds__(256) void convW_kernel(
    const float* __restrict__ Wn, const float* __restrict__ Wr)
{
    const int j = blockIdx.x, k = threadIdx.x;
    float v = (j < DOUTD) ? Wn[(size_t)k * DOUTD + j]
                          : Wr[(size_t)k * DOUTD + (j - DOUTD)];
    __nv_bfloat16 hi = __float2bfloat16(v);
    __nv_bfloat16 lo = __float2bfloat16(v - __bfloat162float(hi));
    __nv_bfloat16* row = g_Bww + (size_t)j * 1024;
    row[k] = hi; row[256 + k] = lo; row[512 + k] = lo; row[768 + k] = hi;
}

// g_xpr cols 0:512 -> xprT [jcat,n] hi/lo (tiled transpose)
__global__ __launch_bounds__(256) void convXpr_kernel()
{
    __shared__ float tile[32][33];
    const int tx = threadIdx.x, ty = threadIdx.y;
    const int n0 = blockIdx.x * 32, j0 = blockIdx.y * 32;
#pragma unroll
    for (int r = 0; r < 4; r++) {
        int nl = ty * 4 + r;
        tile[nl][tx] = g_xpr[(size_t)(n0 + nl) * 1024 + j0 + tx];
    }
    __syncthreads();
#pragma unroll
    for (int r = 0; r < 4; r++) {
        int jl = ty * 4 + r;
        float v = tile[tx][jl];
        __nv_bfloat16 hi = __float2bfloat16(v);
        __nv_bfloat16 lo = __float2bfloat16(v - __bfloat162float(hi));
        g_xprT[(size_t)(j0 + jl) * NP_K + n0 + tx] = hi;
        g_xprT[(size_t)(512 + j0 + jl) * NP_K + n0 + tx] = lo;
    }
}

// D2 [m,1024] -> ET [jcat,m]: fold hi+lo, scale 1/d_e, re-split hi/lo, transpose.
__global__ __launch_bounds__(256) void ep2_kernel()
{
    __shared__ float tile[32][33];
    const int tx = threadIdx.x, ty = threadIdx.y;
    const int m0 = blockIdx.x * 32, j0 = blockIdx.y * 32;
#pragma unroll
    for (int r = 0; r < 4; r++) {
        int ml = ty * 4 + r;
        size_t base = (size_t)(m0 + ml) * 1024;
        int j = j0 + tx;
        tile[ml][tx] = (g_D2[base + j] + g_D2[base + 512 + j]) * g_inv_de[m0 + ml];
    }
    __syncthreads();
#pragma unroll
    for (int r = 0; r < 4; r++) {
        int jl = ty * 4 + r;
        if (m0 + tx < M_EDGES) {
            float v = tile[tx][jl];
            __nv_bfloat16 hi = __float2bfloat16(v);
            __nv_bfloat16 lo = __float2bfloat16(v - __bfloat162float(hi));
            g_ET[(size_t)(j0 + jl) * MP_K + m0 + tx] = hi;
            g_ET[(size_t)(512 + j0 + jl) * MP_K + m0 + tx] = lo;
        }
    }
}

// final: fold D3 hi+lo, /d_v, +residual, LayerNorm -> out
__device__ __forceinline__ float block_sum_256(float v, float* red)
{
#pragma unroll
    for (int o = 16; o > 0; o >>= 1) v += __shfl_xor_sync(0xffffffffu, v, o);
    int w = threadIdx.x >> 5;
    if ((threadIdx.x & 31) == 0) red[w] = v;
    __syncthreads();
    if (threadIdx.x < 32) {
        float r = (threadIdx.x < 8) ? red[threadIdx.x] : 0.0f;
#pragma unroll
        for (int o = 4; o > 0; o >>= 1) r += __shfl_xor_sync(0xffffffffu, r, o);
        if (threadIdx.x == 0) red[0] = r;
    }
    __syncthreads();
    float res = red[0];
    __syncthreads();
    return res;
}

__global__ __launch_bounds__(256) void ln_kernel(
    const float* __restrict__ gamma, const float* __restrict__ beta,
    float* __restrict__ out)
{
    __shared__ float red[8];
    const int n = blockIdx.x, t = threadIdx.x;
    const float inv_dv = g_inv_dv[n];
    const size_t base = (size_t)n * 1024;
    float2 a = *(const float2*)&g_D3[base + t * 2];
    float2 b = *(const float2*)&g_D3[base + 512 + t * 2];
    float2 r = *(const float2*)&g_xpr[base + 512 + t * 2];
    float hx = (a.x + b.x) * inv_dv + r.x;
    float hy = (a.y + b.y) * inv_dv + r.y;
    float mu = block_sum_256(hx + hy, red) * (1.0f / DOUTD);
    float dx = hx - mu, dy = hy - mu;
    float var = block_sum_256(dx * dx + dy * dy, red) * (1.0f / DOUTD);
    float rs = rsqrtf(var + 1e-5f);
    float2 g = *(const float2*)&gamma[t * 2];
    float2 be = *(const float2*)&beta[t * 2];
    float* o = out + (size_t)n * DOUTD;
    o[t * 2 + 0] = dx * rs * g.x + be.x;
    o[t * 2 + 1] = dy * rs * g.y + be.y;
}

// ============================== launch ==============================
extern "C" void kernel_launch(void* const* d_in, const int* in_sizes, int n_in,
                              void* d_out, int out_size)
{
    const float* x     = (const float*)d_in[0];
    const float* H     = (const float*)d_in[1];
    const float* Wn    = (const float*)d_in[2];
    const float* Wr    = (const float*)d_in[3];
    const float* gamma = (const float*)d_in[4];
    const float* beta  = (const float*)d_in[5];
    float* out = (float*)d_out;

    cudaFuncSetAttribute(mma_kernel, cudaFuncAttributeMaxDynamicSharedMemorySize, SMEM_MMA);

    __nv_bfloat16 *Axx, *Bww, *xprT, *Hbf, *Ht, *ET;
    float *xpr, *D2, *D3;
    cudaGetSymbolAddress((void**)&Axx, g_Axx);
    cudaGetSymbolAddress((void**)&Bww, g_Bww);
    cudaGetSymbolAddress((void**)&xpr, g_xpr);
    cudaGetSymbolAddress((void**)&xprT, g_xprT);
    cudaGetSymbolAddress((void**)&Hbf, g_Hbf);
    cudaGetSymbolAddress((void**)&Ht, g_Ht);
    cudaGetSymbolAddress((void**)&ET, g_ET);
    cudaGetSymbolAddress((void**)&D2, g_D2);
    cudaGetSymbolAddress((void**)&D3, g_D3);

    zero_sums_kernel<<<79, 256>>>();
    convH_kernel<<<dim3(157, 625), dim3(32, 8)>>>(H);
    deg_fin_kernel<<<79, 256>>>();

    convX_kernel<<<N_NODES, 256>>>(x);
    convW_kernel<<<1024, 256>>>(Wn, Wr);

    // GEMM1: g_xpr[n,1024] = Axx @ Bww^T   (K=1024 -> 32 iters)
    mma_kernel<<<dim3(157, 4), 256, SMEM_MMA>>>(Axx, Bww, xpr, 1024, 32);

    convXpr_kernel<<<dim3(625, 16), dim3(32, 8)>>>();

    // GEMM2: D2[m,1024] = Ht @ xprT^T      (K=20032 -> 626 iters)
    mma_kernel<<<dim3(40, 4), 256, SMEM_MMA>>>(Ht, xprT, D2, NP_K, 626);

    ep2_kernel<<<dim3(157, 16), dim3(32, 8)>>>();

    // GEMM3: D3[n,1024] = Hbf @ ET^T       (K=5056 -> 158 iters)
    mma_kernel<<<dim3(157, 4), 256, SMEM_MMA>>>(Hbf, ET, D3, MP_K, 158);

    ln_kernel<<<N_NODES, 256>>>(gamma, beta, out);
}

// round 7
// speedup vs baseline: 3.8779x; 1.3338x over previous
#include <cuda_runtime.h>
#include <cuda_bf16.h>
#include <cstdint>

#define N_NODES 20000
#define M_EDGES 5000
#define DIN 256
#define DOUTD 512

// padded dims
#define NP_M 20096            // N padded to 157*128 (MMA M tiles)
#define NP_K 20032            // N padded to 313*64
#define MP_M 5120             // M padded to 40*128
#define MP_K 5056             // M padded to 79*64
#define KXW 768               // GEMM1 K: [xh|xl|xh] (xl*wl term dropped)

// -------- scratch (__device__ globals are zero-initialized; pad regions are
// never written, so padding stays zero across all launches) --------
__device__ __nv_bfloat16 g_Axx[(size_t)NP_M * KXW];      // [n, 768] = [xh|xl|xh]
__device__ __nv_bfloat16 g_Bww[(size_t)1024 * KXW];      // [jcat, 768] = [wh|wh|wl]
__device__ float         g_xpr[(size_t)NP_M * 1024];     // [n, 1024]: 0:512 x@Wn, 512:1024 x@Wr
__device__ __nv_bfloat16 g_xprT[(size_t)1024 * NP_K];    // [jcat, n]: rows 0:512 hi, 512:1024 lo
__device__ __nv_bfloat16 g_Hbf[(size_t)NP_M * MP_K];     // [n, m] bf16
__device__ __nv_bfloat16 g_Ht[(size_t)MP_M * NP_K];      // [m, n] bf16 (transpose)
__device__ __nv_bfloat16 g_ET[(size_t)1024 * MP_K];      // [jcat, m]: rows 0:512 hi, 512:1024 lo
__device__ float         g_D2[(size_t)4 * MP_M * 1024];  // 4 K-split slabs [m, jcat]
__device__ float         g_D3[(size_t)NP_M * 1024];      // [n, jcat]
__device__ float         g_dv_sum[N_NODES];
__device__ float         g_de_sum[MP_M];
__device__ float         g_inv_dv[N_NODES];
__device__ float         g_inv_de[MP_M];

// ============================ helpers ============================
__device__ __forceinline__ uint32_t smem_u32(const void* p) {
    uint32_t a;
    asm("{ .reg .u64 t; cvta.to.shared.u64 t, %1; cvt.u32.u64 %0, t; }" : "=r"(a) : "l"(p));
    return a;
}
__device__ __forceinline__ void cp16(uint32_t dst, const void* src) {
    asm volatile("cp.async.cg.shared.global [%0], [%1], 16;" :: "r"(dst), "l"(src));
}
#define CP_COMMIT() asm volatile("cp.async.commit_group;" ::: "memory")
#define CP_WAIT(n)  asm volatile("cp.async.wait_group %0;" :: "n"(n) : "memory")

__device__ __forceinline__ void ldsm4(uint32_t* r, uint32_t addr) {
    asm volatile("ldmatrix.sync.aligned.m8n8.x4.shared.b16 {%0,%1,%2,%3}, [%4];"
        : "=r"(r[0]), "=r"(r[1]), "=r"(r[2]), "=r"(r[3]) : "r"(addr));
}
__device__ __forceinline__ void mma16816(float* c, const uint32_t* a,
                                         uint32_t b0, uint32_t b1) {
    asm volatile(
        "mma.sync.aligned.m16n8k16.row.col.f32.bf16.bf16.f32 "
        "{%0,%1,%2,%3}, {%4,%5,%6,%7}, {%8,%9}, {%0,%1,%2,%3};"
        : "+f"(c[0]), "+f"(c[1]), "+f"(c[2]), "+f"(c[3])
        : "r"(a[0]), "r"(a[1]), "r"(a[2]), "r"(a[3]), "r"(b0), "r"(b1));
}

// ============================ MMA GEMM =============================
// D[row0:+128, col0:+256] (+ z*dzstride) = A[rows,K] @ B[cols,K]^T
// A,B: K-major bf16, row stride ldab (elements). D fp32 row-major, ld=1024.
// BM=128, BN=256, BK=64, 256 threads (8 warps, 2m x 4n), 3-stage cp.async,
// double-buffered ldmatrix fragments, optional K-split over blockIdx.z.
#define STAGES 3
#define PITCH 144             // 64 bf16 = 128B + 16B pad (conflict-free)
#define ST_A (128 * PITCH)    // 18432
#define ST_B (256 * PITCH)    // 36864
#define ST_SZ (ST_A + ST_B)   // 55296
#define SMEM_MMA (ST_SZ * STAGES)

__global__ __launch_bounds__(256) void mma_kernel(
    const __nv_bfloat16* __restrict__ A, const __nv_bfloat16* __restrict__ B,
    float* __restrict__ D, int ldab,
    int total_chunks, int chunks_per_z, long long dzstride)
{
    extern __shared__ char dynsmem[];
    const uint32_t sb = smem_u32(dynsmem);
    const int tid = threadIdx.x;
    const int lane = tid & 31, wid = tid >> 5;
    const int wm = wid & 1, wn = wid >> 1;       // warp grid 2 x 4
    const int row0 = blockIdx.x * 128;
    const int col0 = blockIdx.y * 256;

    const int kc0 = blockIdx.z * chunks_per_z;
    int nch = total_chunks - kc0; if (nch > chunks_per_z) nch = chunks_per_z;
    D += (long long)blockIdx.z * dzstride;

    const __nv_bfloat16* Ab = A + (size_t)row0 * ldab + (size_t)kc0 * 64;
    const __nv_bfloat16* Bb = B + (size_t)col0 * ldab + (size_t)kc0 * 64;

    // ldmatrix lane addressing
    const int ra = (lane & 7) + ((lane >> 3) & 1) * 8;  // A row add
    const int ka = (lane >> 4) * 8;                     // A k add
    const int rb = (lane & 7) + (lane >> 4) * 8;        // B row add
    const int kb = ((lane >> 3) & 1) * 8;               // B k add
    const uint32_t aoff = (wm * 64 + ra) * PITCH + ka * 2;
    const uint32_t boff = (wn * 64 + rb) * PITCH + kb * 2;

    const int lr = tid >> 3, ls = tid & 7;              // cp.async row/seg

    float acc[4][8][4];
#pragma unroll
    for (int i = 0; i < 4; i++)
#pragma unroll
        for (int j = 0; j < 8; j++)
#pragma unroll
            for (int k = 0; k < 4; k++) acc[i][j][k] = 0.f;

    auto issue_load = [&](int buf, int chunk) {
        const uint32_t sa = sb + buf * ST_SZ;
        const uint32_t sB = sa + ST_A;
        const __nv_bfloat16* Ak = Ab + (size_t)chunk * 64;
        const __nv_bfloat16* Bk = Bb + (size_t)chunk * 64;
#pragma unroll
        for (int i = 0; i < 4; i++) {
            int r = lr + i * 32;
            cp16(sa + r * PITCH + ls * 16, Ak + (size_t)r * ldab + ls * 8);
        }
#pragma unroll
        for (int i = 0; i < 8; i++) {
            int r = lr + i * 32;
            cp16(sB + r * PITCH + ls * 16, Bk + (size_t)r * ldab + ls * 8);
        }
    };

    // prologue
    issue_load(0, 0); CP_COMMIT();
    if (nch > 1) issue_load(1, 1);
    CP_COMMIT();

    for (int it = 0; it < nch; it++) {
        CP_WAIT(1);
        __syncthreads();
        const uint32_t sa = sb + (it % STAGES) * ST_SZ;
        const uint32_t sB = sa + ST_A;

        uint32_t afr[2][4][4], bfr[2][4][4];
        // prefetch ks=0
#pragma unroll
        for (int mb = 0; mb < 4; mb++) ldsm4(afr[0][mb], sa + aoff + mb * 16 * PITCH);
#pragma unroll
        for (int np = 0; np < 4; np++) ldsm4(bfr[0][np], sB + boff + np * 16 * PITCH);

#pragma unroll
        for (int ks = 0; ks < 4; ks++) {
            const int cur = ks & 1, nxt = cur ^ 1;
            if (ks < 3) {
                const uint32_t ko = (ks + 1) * 32;
#pragma unroll
                for (int mb = 0; mb < 4; mb++)
                    ldsm4(afr[nxt][mb], sa + aoff + mb * 16 * PITCH + ko);
#pragma unroll
                for (int np = 0; np < 4; np++)
                    ldsm4(bfr[nxt][np], sB + boff + np * 16 * PITCH + ko);
            }
#pragma unroll
            for (int mb = 0; mb < 4; mb++)
#pragma unroll
                for (int np = 0; np < 4; np++) {
                    mma16816(acc[mb][np * 2], afr[cur][mb], bfr[cur][np][0], bfr[cur][np][1]);
                    mma16816(acc[mb][np * 2 + 1], afr[cur][mb], bfr[cur][np][2], bfr[cur][np][3]);
                }
        }
        __syncthreads();
        if (it + 2 < nch) issue_load((it + 2) % STAGES, it + 2);
        CP_COMMIT();
    }

    // epilogue: direct fp32 stores
    const int rbase = row0 + wm * 64 + (lane >> 2);
    const int cbase = col0 + wn * 64 + (lane & 3) * 2;
#pragma unroll
    for (int mb = 0; mb < 4; mb++) {
#pragma unroll
        for (int nb = 0; nb < 8; nb++) {
            const int r = rbase + mb * 16;
            const int c = cbase + nb * 8;
            *(float2*)&D[(size_t)r * 1024 + c] = make_float2(acc[mb][nb][0], acc[mb][nb][1]);
            *(float2*)&D[(size_t)(r + 8) * 1024 + c] = make_float2(acc[mb][nb][2], acc[mb][nb][3]);
        }
    }
}

// ===================== conversion / epilogue kernels =====================
__global__ void zero_sums_kernel()
{
    int i = blockIdx.x * blockDim.x + threadIdx.x;
    if (i < N_NODES) g_dv_sum[i] = 0.f;
    if (i < MP_M) g_de_sum[i] = 0.f;
}

// H -> H_bf [n,m], Ht [m,n] (bf16), plus degree partial sums. 32x32 tiles.
__global__ __launch_bounds__(256) void convH_kernel(const float* __restrict__ H)
{
    __shared__ float tile[32][33];
    __shared__ float colpart[8][32];
    const int tx = threadIdx.x, ty = threadIdx.y;
    const int m0 = blockIdx.x * 32, n0 = blockIdx.y * 32;
    const int m = m0 + tx;
    float v[4];
#pragma unroll
    for (int r = 0; r < 4; r++) {
        int n = n0 + ty * 4 + r;
        float val = (m < M_EDGES) ? H[(size_t)n * M_EDGES + m] : 0.f;
        v[r] = val;
        tile[ty * 4 + r][tx] = val;
        if (m < M_EDGES)
            g_Hbf[(size_t)n * MP_K + m] = __float2bfloat16(val);
    }
#pragma unroll
    for (int r = 0; r < 4; r++) {
        float s = v[r];
#pragma unroll
        for (int o = 16; o > 0; o >>= 1) s += __shfl_xor_sync(0xffffffffu, s, o);
        if (tx == 0) atomicAdd(&g_dv_sum[n0 + ty * 4 + r], s);
    }
    colpart[ty][tx] = v[0] + v[1] + v[2] + v[3];
    __syncthreads();
    if (ty == 0 && m < M_EDGES) {
        float s = 0.f;
#pragma unroll
        for (int w = 0; w < 8; w++) s += colpart[w][tx];
        atomicAdd(&g_de_sum[m], s);
    }
#pragma unroll
    for (int r = 0; r < 4; r++) {
        int ml = ty * 4 + r;
        if (m0 + ml < M_EDGES)
            g_Ht[(size_t)(m0 + ml) * NP_K + n0 + tx] = __float2bfloat16(tile[tx][ml]);
    }
}

__global__ void deg_fin_kernel()
{
    int i = blockIdx.x * blockDim.x + threadIdx.x;
    if (i < N_NODES) g_inv_dv[i] = 1.0f / fmaxf(g_dv_sum[i], 1.0f);
    if (i < M_EDGES) g_inv_de[i] = 1.0f / fmaxf(g_de_sum[i], 1.0f);
}

// x [n,256] -> Axx [n,768] = [xh | xl | xh]
__global__ __launch_bounds__(256) void convX_kernel(const float* __restrict__ x)
{
    const int n = blockIdx.x, k = threadIdx.x;
    float v = x[(size_t)n * DIN + k];
    __nv_bfloat16 hi = __float2bfloat16(v);
    __nv_bfloat16 lo = __float2bfloat16(v - __bfloat162float(hi));
    __nv_bfloat16* row = g_Axx + (size_t)n * KXW;
    row[k] = hi; row[256 + k] = lo; row[512 + k] = hi;
}

// Wn,Wr [256,512] -> Bww [jcat,768] = [wh | wh | wl]
__global__ __launch_bounds__(256) void convW_kernel(
    const float* __restrict__ Wn, const float* __restrict__ Wr)
{
    const int j = blockIdx.x, k = threadIdx.x;
    float v = (j < DOUTD) ? Wn[(size_t)k * DOUTD + j]
                          : Wr[(size_t)k * DOUTD + (j - DOUTD)];
    __nv_bfloat16 hi = __float2bfloat16(v);
    __nv_bfloat16 lo = __float2bfloat16(v - __bfloat162float(hi));
    __nv_bfloat16* row = g_Bww + (size_t)j * KXW;
    row[k] = hi; row[256 + k] = hi; row[512 + k] = lo;
}

// g_xpr cols 0:512 -> xprT [jcat,n] hi/lo (tiled transpose)
__global__ __launch_bounds__(256) void convXpr_kernel()
{
    __shared__ float tile[32][33];
    const int tx = threadIdx.x, ty = threadIdx.y;
    const int n0 = blockIdx.x * 32, j0 = blockIdx.y * 32;
#pragma unroll
    for (int r = 0; r < 4; r++) {
        int nl = ty * 4 + r;
        tile[nl][tx] = g_xpr[(size_t)(n0 + nl) * 1024 + j0 + tx];
    }
    __syncthreads();
#pragma unroll
    for (int r = 0; r < 4; r++) {
        int jl = ty * 4 + r;
        float v = tile[tx][jl];
        __nv_bfloat16 hi = __float2bfloat16(v);
        __nv_bfloat16 lo = __float2bfloat16(v - __bfloat162float(hi));
        g_xprT[(size_t)(j0 + jl) * NP_K + n0 + tx] = hi;
        g_xprT[(size_t)(512 + j0 + jl) * NP_K + n0 + tx] = lo;
    }
}

// D2 slabs -> ET [jcat,m]: fold hi+lo & 4 K-splits, *1/d_e, re-split, transpose.
__global__ __launch_bounds__(256) void ep2_kernel()
{
    __shared__ float tile[32][33];
    const int tx = threadIdx.x, ty = threadIdx.y;
    const int m0 = blockIdx.x * 32, j0 = blockIdx.y * 32;
#pragma unroll
    for (int r = 0; r < 4; r++) {
        int ml = ty * 4 + r;
        size_t base = (size_t)(m0 + ml) * 1024;
        int j = j0 + tx;
        float e = 0.f;
#pragma unroll
        for (int z = 0; z < 4; z++) {
            const float* Dz = g_D2 + (size_t)z * MP_M * 1024;
            e += Dz[base + j] + Dz[base + 512 + j];
        }
        tile[ml][tx] = e * g_inv_de[m0 + ml];
    }
    __syncthreads();
#pragma unroll
    for (int r = 0; r < 4; r++) {
        int jl = ty * 4 + r;
        if (m0 + tx < M_EDGES) {
            float v = tile[tx][jl];
            __nv_bfloat16 hi = __float2bfloat16(v);
            __nv_bfloat16 lo = __float2bfloat16(v - __bfloat162float(hi));
            g_ET[(size_t)(j0 + jl) * MP_K + m0 + tx] = hi;
            g_ET[(size_t)(512 + j0 + jl) * MP_K + m0 + tx] = lo;
        }
    }
}

// final: fold D3 hi+lo, /d_v, +residual, LayerNorm -> out
__device__ __forceinline__ float block_sum_256(float v, float* red)
{
#pragma unroll
    for (int o = 16; o > 0; o >>= 1) v += __shfl_xor_sync(0xffffffffu, v, o);
    int w = threadIdx.x >> 5;
    if ((threadIdx.x & 31) == 0) red[w] = v;
    __syncthreads();
    if (threadIdx.x < 32) {
        float r = (threadIdx.x < 8) ? red[threadIdx.x] : 0.0f;
#pragma unroll
        for (int o = 4; o > 0; o >>= 1) r += __shfl_xor_sync(0xffffffffu, r, o);
        if (threadIdx.x == 0) red[0] = r;
    }
    __syncthreads();
    float res = red[0];
    __syncthreads();
    return res;
}

__global__ __launch_bounds__(256) void ln_kernel(
    const float* __restrict__ gamma, const float* __restrict__ beta,
    float* __restrict__ out)
{
    __shared__ float red[8];
    const int n = blockIdx.x, t = threadIdx.x;
    const float inv_dv = g_inv_dv[n];
    const size_t base = (size_t)n * 1024;
    float2 a = *(const float2*)&g_D3[base + t * 2];
    float2 b = *(const float2*)&g_D3[base + 512 + t * 2];
    float2 r = *(const float2*)&g_xpr[base + 512 + t * 2];
    float hx = (a.x + b.x) * inv_dv + r.x;
    float hy = (a.y + b.y) * inv_dv + r.y;
    float mu = block_sum_256(hx + hy, red) * (1.0f / DOUTD);
    float dx = hx - mu, dy = hy - mu;
    float var = block_sum_256(dx * dx + dy * dy, red) * (1.0f / DOUTD);
    float rs = rsqrtf(var + 1e-5f);
    float2 g = *(const float2*)&gamma[t * 2];
    float2 be = *(const float2*)&beta[t * 2];
    float* o = out + (size_t)n * DOUTD;
    o[t * 2 + 0] = dx * rs * g.x + be.x;
    o[t * 2 + 1] = dy * rs * g.y + be.y;
}

// ============================== launch ==============================
extern "C" void kernel_launch(void* const* d_in, const int* in_sizes, int n_in,
                              void* d_out, int out_size)
{
    const float* x     = (const float*)d_in[0];
    const float* H     = (const float*)d_in[1];
    const float* Wn    = (const float*)d_in[2];
    const float* Wr    = (const float*)d_in[3];
    const float* gamma = (const float*)d_in[4];
    const float* beta  = (const float*)d_in[5];
    float* out = (float*)d_out;

    cudaFuncSetAttribute(mma_kernel, cudaFuncAttributeMaxDynamicSharedMemorySize, SMEM_MMA);

    __nv_bfloat16 *Axx, *Bww, *xprT, *Hbf, *Ht, *ET;
    float *xpr, *D2, *D3;
    cudaGetSymbolAddress((void**)&Axx, g_Axx);
    cudaGetSymbolAddress((void**)&Bww, g_Bww);
    cudaGetSymbolAddress((void**)&xpr, g_xpr);
    cudaGetSymbolAddress((void**)&xprT, g_xprT);
    cudaGetSymbolAddress((void**)&Hbf, g_Hbf);
    cudaGetSymbolAddress((void**)&Ht, g_Ht);
    cudaGetSymbolAddress((void**)&ET, g_ET);
    cudaGetSymbolAddress((void**)&D2, g_D2);
    cudaGetSymbolAddress((void**)&D3, g_D3);

    // order chosen so GEMM1 lands in the ncu-profiled slot (4th launch)
    zero_sums_kernel<<<79, 256>>>();
    convX_kernel<<<N_NODES, 256>>>(x);
    convW_kernel<<<1024, 256>>>(Wn, Wr);

    // GEMM1: g_xpr[n,1024] = Axx @ Bww^T   (K=768 -> 12 chunks)
    mma_kernel<<<dim3(157, 4, 1), 256, SMEM_MMA>>>(Axx, Bww, xpr, KXW, 12, 12, 0);

    convH_kernel<<<dim3(157, 625), dim3(32, 8)>>>(H);
    deg_fin_kernel<<<79, 256>>>();
    convXpr_kernel<<<dim3(625, 16), dim3(32, 8)>>>();

    // GEMM2: D2[z][m,1024] = Ht @ xprT^T   (313 chunks, K-split 4)
    mma_kernel<<<dim3(40, 4, 4), 256, SMEM_MMA>>>(Ht, xprT, D2, NP_K, 313, 79,
                                                  (long long)MP_M * 1024);

    ep2_kernel<<<dim3(157, 16), dim3(32, 8)>>>();

    // GEMM3: D3[n,1024] = Hbf @ ET^T       (79 chunks)
    mma_kernel<<<dim3(157, 4, 1), 256, SMEM_MMA>>>(Hbf, ET, D3, MP_K, 79, 79, 0);

    ln_kernel<<<N_NODES, 256>>>(gamma, beta, out);
}

// round 8
// speedup vs baseline: 4.1252x; 1.0638x over previous
#include <cuda_runtime.h>
#include <cuda_bf16.h>
#include <cstdint>

#define N_NODES 20000
#define M_EDGES 5000
#define DIN 256
#define DOUTD 512

// padded dims
#define NP_M 20096            // N padded to 157*128 (MMA M tiles)
#define NP_K 20032            // N padded to 313*64
#define MP_M 5120             // M padded to 40*128
#define MP_K 5056             // M padded to 79*64
#define KXW 768               // GEMM1 K: [xh|xl|xh] (xl*wl term dropped)

// -------- scratch (__device__ globals are zero-initialized; pad regions are
// never written, so padding stays zero across all launches) --------
__device__ __nv_bfloat16 g_Axx[(size_t)NP_M * KXW];      // [n, 768] = [xh|xl|xh]
__device__ __nv_bfloat16 g_Bww[(size_t)1024 * KXW];      // [jcat, 768] = [wh|wh|wl]
__device__ float         g_xpr[(size_t)NP_M * 1024];     // [n, 1024]: 0:512 x@Wn, 512:1024 x@Wr
__device__ __nv_bfloat16 g_xprT[(size_t)1024 * NP_K];    // [jcat, n]: rows 0:512 hi, 512:1024 lo
__device__ __nv_bfloat16 g_Hbf[(size_t)NP_M * MP_K];     // [n, m] bf16
__device__ __nv_bfloat16 g_Ht[(size_t)MP_M * NP_K];      // [m, n] bf16 (transpose)
__device__ __nv_bfloat16 g_ET[(size_t)1024 * MP_K];      // [jcat, m]: rows 0:512 hi, 512:1024 lo
__device__ float         g_D2[(size_t)4 * MP_M * 1024];  // 4 K-split slabs [m, jcat]
__device__ float         g_D3[(size_t)NP_M * 1024];      // [n, jcat]
__device__ float         g_dv_sum[N_NODES];
__device__ float         g_de_sum[MP_M];
__device__ float         g_inv_dv[N_NODES];
__device__ float         g_inv_de[MP_M];

// ============================ helpers ============================
__device__ __forceinline__ uint32_t smem_u32(const void* p) {
    uint32_t a;
    asm("{ .reg .u64 t; cvta.to.shared.u64 t, %1; cvt.u32.u64 %0, t; }" : "=r"(a) : "l"(p));
    return a;
}
__device__ __forceinline__ void cp16(uint32_t dst, const void* src) {
    asm volatile("cp.async.cg.shared.global [%0], [%1], 16;" :: "r"(dst), "l"(src));
}
#define CP_COMMIT() asm volatile("cp.async.commit_group;" ::: "memory")
#define CP_WAIT(n)  asm volatile("cp.async.wait_group %0;" :: "n"(n) : "memory")

__device__ __forceinline__ void ldsm4(uint32_t* r, uint32_t addr) {
    asm volatile("ldmatrix.sync.aligned.m8n8.x4.shared.b16 {%0,%1,%2,%3}, [%4];"
        : "=r"(r[0]), "=r"(r[1]), "=r"(r[2]), "=r"(r[3]) : "r"(addr));
}
__device__ __forceinline__ void mma16816(float* c, const uint32_t* a,
                                         uint32_t b0, uint32_t b1) {
    asm volatile(
        "mma.sync.aligned.m16n8k16.row.col.f32.bf16.bf16.f32 "
        "{%0,%1,%2,%3}, {%4,%5,%6,%7}, {%8,%9}, {%0,%1,%2,%3};"
        : "+f"(c[0]), "+f"(c[1]), "+f"(c[2]), "+f"(c[3])
        : "r"(a[0]), "r"(a[1]), "r"(a[2]), "r"(a[3]), "r"(b0), "r"(b1));
}

// ============================ MMA GEMM =============================
// D[row0:+128, col0:+128] (+ z*dzstride) = A[rows,K] @ B[cols,K]^T
// A,B: K-major bf16, row stride ldab (elements). D fp32 row-major, ld=1024.
// BM=128, BN=128, BK=64, 256 threads (8 warps, 2m x 4n -> 64x32 warp tile),
// 3-stage cp.async, double-buffered ldmatrix fragments, 2 CTAs/SM.
#define STAGES 3
#define PITCH 144             // 64 bf16 = 128B + 16B pad (conflict-free)
#define ST_A (128 * PITCH)    // 18432
#define ST_B (128 * PITCH)    // 18432
#define ST_SZ (ST_A + ST_B)   // 36864
#define SMEM_MMA (ST_SZ * STAGES)   // 110592 -> 2 CTAs per SM

__global__ __launch_bounds__(256, 2) void mma_kernel(
    const __nv_bfloat16* __restrict__ A, const __nv_bfloat16* __restrict__ B,
    float* __restrict__ D, int ldab,
    int total_chunks, int chunks_per_z, long long dzstride)
{
    extern __shared__ char dynsmem[];
    const uint32_t sb = smem_u32(dynsmem);
    const int tid = threadIdx.x;
    const int lane = tid & 31, wid = tid >> 5;
    const int wm = wid & 1, wn = wid >> 1;       // warp grid 2m x 4n
    const int row0 = blockIdx.x * 128;
    const int col0 = blockIdx.y * 128;

    const int kc0 = blockIdx.z * chunks_per_z;
    int nch = total_chunks - kc0; if (nch > chunks_per_z) nch = chunks_per_z;
    D += (long long)blockIdx.z * dzstride;

    const __nv_bfloat16* Ab = A + (size_t)row0 * ldab + (size_t)kc0 * 64;
    const __nv_bfloat16* Bb = B + (size_t)col0 * ldab + (size_t)kc0 * 64;

    // ldmatrix lane addressing
    const int ra = (lane & 7) + ((lane >> 3) & 1) * 8;  // A row add
    const int ka = (lane >> 4) * 8;                     // A k add
    const int rb = (lane & 7) + (lane >> 4) * 8;        // B row add
    const int kb = ((lane >> 3) & 1) * 8;               // B k add
    const uint32_t aoff = (wm * 64 + ra) * PITCH + ka * 2;
    const uint32_t boff = (wn * 32 + rb) * PITCH + kb * 2;

    const int lr = tid >> 3, ls = tid & 7;              // cp.async row/seg

    float acc[4][4][4];
#pragma unroll
    for (int i = 0; i < 4; i++)
#pragma unroll
        for (int j = 0; j < 4; j++)
#pragma unroll
            for (int k = 0; k < 4; k++) acc[i][j][k] = 0.f;

    auto issue_load = [&](int buf, int chunk) {
        const uint32_t sa = sb + buf * ST_SZ;
        const uint32_t sB = sa + ST_A;
        const __nv_bfloat16* Ak = Ab + (size_t)chunk * 64;
        const __nv_bfloat16* Bk = Bb + (size_t)chunk * 64;
#pragma unroll
        for (int i = 0; i < 4; i++) {
            int r = lr + i * 32;
            cp16(sa + r * PITCH + ls * 16, Ak + (size_t)r * ldab + ls * 8);
            cp16(sB + r * PITCH + ls * 16, Bk + (size_t)r * ldab + ls * 8);
        }
    };

    // prologue
    issue_load(0, 0); CP_COMMIT();
    if (nch > 1) issue_load(1, 1);
    CP_COMMIT();

    for (int it = 0; it < nch; it++) {
        CP_WAIT(1);
        __syncthreads();
        const uint32_t sa = sb + (it % STAGES) * ST_SZ;
        const uint32_t sB = sa + ST_A;

        uint32_t afr[2][4][4], bfr[2][2][4];
        // prefetch ks=0
#pragma unroll
        for (int mb = 0; mb < 4; mb++) ldsm4(afr[0][mb], sa + aoff + mb * 16 * PITCH);
#pragma unroll
        for (int np = 0; np < 2; np++) ldsm4(bfr[0][np], sB + boff + np * 16 * PITCH);

#pragma unroll
        for (int ks = 0; ks < 4; ks++) {
            const int cur = ks & 1, nxt = cur ^ 1;
            if (ks < 3) {
                const uint32_t ko = (ks + 1) * 32;
#pragma unroll
                for (int mb = 0; mb < 4; mb++)
                    ldsm4(afr[nxt][mb], sa + aoff + mb * 16 * PITCH + ko);
#pragma unroll
                for (int np = 0; np < 2; np++)
                    ldsm4(bfr[nxt][np], sB + boff + np * 16 * PITCH + ko);
            }
#pragma unroll
            for (int mb = 0; mb < 4; mb++)
#pragma unroll
                for (int np = 0; np < 2; np++) {
                    mma16816(acc[mb][np * 2], afr[cur][mb], bfr[cur][np][0], bfr[cur][np][1]);
                    mma16816(acc[mb][np * 2 + 1], afr[cur][mb], bfr[cur][np][2], bfr[cur][np][3]);
                }
        }
        __syncthreads();
        if (it + 2 < nch) issue_load((it + 2) % STAGES, it + 2);
        CP_COMMIT();
    }

    // epilogue: direct fp32 stores
    const int rbase = row0 + wm * 64 + (lane >> 2);
    const int cbase = col0 + wn * 32 + (lane & 3) * 2;
#pragma unroll
    for (int mb = 0; mb < 4; mb++) {
#pragma unroll
        for (int nb = 0; nb < 4; nb++) {
            const int r = rbase + mb * 16;
            const int c = cbase + nb * 8;
            *(float2*)&D[(size_t)r * 1024 + c] = make_float2(acc[mb][nb][0], acc[mb][nb][1]);
            *(float2*)&D[(size_t)(r + 8) * 1024 + c] = make_float2(acc[mb][nb][2], acc[mb][nb][3]);
        }
    }
}

// ===================== conversion / epilogue kernels =====================
__global__ void zero_sums_kernel()
{
    int i = blockIdx.x * blockDim.x + threadIdx.x;
    if (i < N_NODES) g_dv_sum[i] = 0.f;
    if (i < MP_M) g_de_sum[i] = 0.f;
}

// H -> H_bf [n,m], Ht [m,n] (bf16), plus degree partial sums. 32x32 tiles.
__global__ __launch_bounds__(256) void convH_kernel(const float* __restrict__ H)
{
    __shared__ float tile[32][33];
    __shared__ float colpart[8][32];
    const int tx = threadIdx.x, ty = threadIdx.y;
    const int m0 = blockIdx.x * 32, n0 = blockIdx.y * 32;
    const int m = m0 + tx;
    float v[4];
#pragma unroll
    for (int r = 0; r < 4; r++) {
        int n = n0 + ty * 4 + r;
        float val = (m < M_EDGES) ? H[(size_t)n * M_EDGES + m] : 0.f;
        v[r] = val;
        tile[ty * 4 + r][tx] = val;
        if (m < M_EDGES)
            g_Hbf[(size_t)n * MP_K + m] = __float2bfloat16(val);
    }
#pragma unroll
    for (int r = 0; r < 4; r++) {
        float s = v[r];
#pragma unroll
        for (int o = 16; o > 0; o >>= 1) s += __shfl_xor_sync(0xffffffffu, s, o);
        if (tx == 0) atomicAdd(&g_dv_sum[n0 + ty * 4 + r], s);
    }
    colpart[ty][tx] = v[0] + v[1] + v[2] + v[3];
    __syncthreads();
    if (ty == 0 && m < M_EDGES) {
        float s = 0.f;
#pragma unroll
        for (int w = 0; w < 8; w++) s += colpart[w][tx];
        atomicAdd(&g_de_sum[m], s);
    }
#pragma unroll
    for (int r = 0; r < 4; r++) {
        int ml = ty * 4 + r;
        if (m0 + ml < M_EDGES)
            g_Ht[(size_t)(m0 + ml) * NP_K + n0 + tx] = __float2bfloat16(tile[tx][ml]);
    }
}

__global__ void deg_fin_kernel()
{
    int i = blockIdx.x * blockDim.x + threadIdx.x;
    if (i < N_NODES) g_inv_dv[i] = 1.0f / fmaxf(g_dv_sum[i], 1.0f);
    if (i < M_EDGES) g_inv_de[i] = 1.0f / fmaxf(g_de_sum[i], 1.0f);
}

// x [n,256] -> Axx [n,768] = [xh | xl | xh]
__global__ __launch_bounds__(256) void convX_kernel(const float* __restrict__ x)
{
    const int n = blockIdx.x, k = threadIdx.x;
    float v = x[(size_t)n * DIN + k];
    __nv_bfloat16 hi = __float2bfloat16(v);
    __nv_bfloat16 lo = __float2bfloat16(v - __bfloat162float(hi));
    __nv_bfloat16* row = g_Axx + (size_t)n * KXW;
    row[k] = hi; row[256 + k] = lo; row[512 + k] = hi;
}

// Wn,Wr [256,512] -> Bww [jcat,768] = [wh | wh | wl]
__global__ __launch_bounds__(256) void convW_kernel(
    const float* __restrict__ Wn, const float* __restrict__ Wr)
{
    const int j = blockIdx.x, k = threadIdx.x;
    float v = (j < DOUTD) ? Wn[(size_t)k * DOUTD + j]
                          : Wr[(size_t)k * DOUTD + (j - DOUTD)];
    __nv_bfloat16 hi = __float2bfloat16(v);
    __nv_bfloat16 lo = __float2bfloat16(v - __bfloat162float(hi));
    __nv_bfloat16* row = g_Bww + (size_t)j * KXW;
    row[k] = hi; row[256 + k] = hi; row[512 + k] = lo;
}

// g_xpr cols 0:512 -> xprT [jcat,n] hi/lo (tiled transpose)
__global__ __launch_bounds__(256) void convXpr_kernel()
{
    __shared__ float tile[32][33];
    const int tx = threadIdx.x, ty = threadIdx.y;
    const int n0 = blockIdx.x * 32, j0 = blockIdx.y * 32;
#pragma unroll
    for (int r = 0; r < 4; r++) {
        int nl = ty * 4 + r;
        tile[nl][tx] = g_xpr[(size_t)(n0 + nl) * 1024 + j0 + tx];
    }
    __syncthreads();
#pragma unroll
    for (int r = 0; r < 4; r++) {
        int jl = ty * 4 + r;
        float v = tile[tx][jl];
        __nv_bfloat16 hi = __float2bfloat16(v);
        __nv_bfloat16 lo = __float2bfloat16(v - __bfloat162float(hi));
        g_xprT[(size_t)(j0 + jl) * NP_K + n0 + tx] = hi;
        g_xprT[(size_t)(512 + j0 + jl) * NP_K + n0 + tx] = lo;
    }
}

// D2 slabs -> ET [jcat,m]: fold hi+lo & 4 K-splits, *1/d_e, re-split, transpose.
__global__ __launch_bounds__(256) void ep2_kernel()
{
    __shared__ float tile[32][33];
    const int tx = threadIdx.x, ty = threadIdx.y;
    const int m0 = blockIdx.x * 32, j0 = blockIdx.y * 32;
#pragma unroll
    for (int r = 0; r < 4; r++) {
        int ml = ty * 4 + r;
        size_t base = (size_t)(m0 + ml) * 1024;
        int j = j0 + tx;
        float e = 0.f;
#pragma unroll
        for (int z = 0; z < 4; z++) {
            const float* Dz = g_D2 + (size_t)z * MP_M * 1024;
            e += Dz[base + j] + Dz[base + 512 + j];
        }
        tile[ml][tx] = e * g_inv_de[m0 + ml];
    }
    __syncthreads();
#pragma unroll
    for (int r = 0; r < 4; r++) {
        int jl = ty * 4 + r;
        if (m0 + tx < M_EDGES) {
            float v = tile[tx][jl];
            __nv_bfloat16 hi = __float2bfloat16(v);
            __nv_bfloat16 lo = __float2bfloat16(v - __bfloat162float(hi));
            g_ET[(size_t)(j0 + jl) * MP_K + m0 + tx] = hi;
            g_ET[(size_t)(512 + j0 + jl) * MP_K + m0 + tx] = lo;
        }
    }
}

// final: fold D3 hi+lo, /d_v, +residual, LayerNorm -> out
__device__ __forceinline__ float block_sum_256(float v, float* red)
{
#pragma unroll
    for (int o = 16; o > 0; o >>= 1) v += __shfl_xor_sync(0xffffffffu, v, o);
    int w = threadIdx.x >> 5;
    if ((threadIdx.x & 31) == 0) red[w] = v;
    __syncthreads();
    if (threadIdx.x < 32) {
        float r = (threadIdx.x < 8) ? red[threadIdx.x] : 0.0f;
#pragma unroll
        for (int o = 4; o > 0; o >>= 1) r += __shfl_xor_sync(0xffffffffu, r, o);
        if (threadIdx.x == 0) red[0] = r;
    }
    __syncthreads();
    float res = red[0];
    __syncthreads();
    return res;
}

__global__ __launch_bounds__(256) void ln_kernel(
    const float* __restrict__ gamma, const float* __restrict__ beta,
    float* __restrict__ out)
{
    __shared__ float red[8];
    const int n = blockIdx.x, t = threadIdx.x;
    const float inv_dv = g_inv_dv[n];
    const size_t base = (size_t)n * 1024;
    float2 a = *(const float2*)&g_D3[base + t * 2];
    float2 b = *(const float2*)&g_D3[base + 512 + t * 2];
    float2 r = *(const float2*)&g_xpr[base + 512 + t * 2];
    float hx = (a.x + b.x) * inv_dv + r.x;
    float hy = (a.y + b.y) * inv_dv + r.y;
    float mu = block_sum_256(hx + hy, red) * (1.0f / DOUTD);
    float dx = hx - mu, dy = hy - mu;
    float var = block_sum_256(dx * dx + dy * dy, red) * (1.0f / DOUTD);
    float rs = rsqrtf(var + 1e-5f);
    float2 g = *(const float2*)&gamma[t * 2];
    float2 be = *(const float2*)&beta[t * 2];
    float* o = out + (size_t)n * DOUTD;
    o[t * 2 + 0] = dx * rs * g.x + be.x;
    o[t * 2 + 1] = dy * rs * g.y + be.y;
}

// ============================== launch ==============================
extern "C" void kernel_launch(void* const* d_in, const int* in_sizes, int n_in,
                              void* d_out, int out_size)
{
    const float* x     = (const float*)d_in[0];
    const float* H     = (const float*)d_in[1];
    const float* Wn    = (const float*)d_in[2];
    const float* Wr    = (const float*)d_in[3];
    const float* gamma = (const float*)d_in[4];
    const float* beta  = (const float*)d_in[5];
    float* out = (float*)d_out;

    cudaFuncSetAttribute(mma_kernel, cudaFuncAttributeMaxDynamicSharedMemorySize, SMEM_MMA);

    __nv_bfloat16 *Axx, *Bww, *xprT, *Hbf, *Ht, *ET;
    float *xpr, *D2, *D3;
    cudaGetSymbolAddress((void**)&Axx, g_Axx);
    cudaGetSymbolAddress((void**)&Bww, g_Bww);
    cudaGetSymbolAddress((void**)&xpr, g_xpr);
    cudaGetSymbolAddress((void**)&xprT, g_xprT);
    cudaGetSymbolAddress((void**)&Hbf, g_Hbf);
    cudaGetSymbolAddress((void**)&Ht, g_Ht);
    cudaGetSymbolAddress((void**)&ET, g_ET);
    cudaGetSymbolAddress((void**)&D2, g_D2);
    cudaGetSymbolAddress((void**)&D3, g_D3);

    zero_sums_kernel<<<79, 256>>>();
    convX_kernel<<<N_NODES, 256>>>(x);
    convW_kernel<<<1024, 256>>>(Wn, Wr);

    // GEMM1: g_xpr[n,1024] = Axx @ Bww^T   (K=768 -> 12 chunks)
    mma_kernel<<<dim3(157, 8, 1), 256, SMEM_MMA>>>(Axx, Bww, xpr, KXW, 12, 12, 0);

    convH_kernel<<<dim3(157, 625), dim3(32, 8)>>>(H);
    deg_fin_kernel<<<79, 256>>>();
    convXpr_kernel<<<dim3(625, 16), dim3(32, 8)>>>();

    // GEMM2: D2[z][m,1024] = Ht @ xprT^T   (313 chunks, K-split 4)
    mma_kernel<<<dim3(40, 8, 4), 256, SMEM_MMA>>>(Ht, xprT, D2, NP_K, 313, 79,
                                                  (long long)MP_M * 1024);

    ep2_kernel<<<dim3(157, 16), dim3(32, 8)>>>();

    // GEMM3: D3[n,1024] = Hbf @ ET^T       (79 chunks)
    mma_kernel<<<dim3(157, 8, 1), 256, SMEM_MMA>>>(Hbf, ET, D3, MP_K, 79, 79, 0);

    ln_kernel<<<N_NODES, 256>>>(gamma, beta, out);
}

// round 9
// speedup vs baseline: 6.2387x; 1.5123x over previous
#include <cuda_runtime.h>
#include <cuda_bf16.h>
#include <cstdint>

#define N_NODES 20000
#define M_EDGES 5000
#define DIN 256
#define DOUTD 512

// padded dims
#define NP_M 20096            // N padded to 157*128
#define NP_K2 20096           // K over nodes, padded to 157*128 (s8 bytes)
#define MP_M 5120             // M padded to 40*128
#define MP_K2 5120            // K over edges, padded to 40*128 (s8 bytes)
#define KXW 768               // GEMM1 K: [xh|xl|xh] (xl*wl term dropped)

#define SX_INV 2048.0f        // xpr digit scale: xpr ~= (1/2048)*(dh*128+dl)
#define SX_VAL (1.0f/2048.0f)
#define QCLAMP 16255

// -------- scratch (__device__ globals zero-initialized; pads never written) --------
__device__ __nv_bfloat16 g_Axx[(size_t)NP_M * KXW];      // [n,768] = [xh|xl|xh]
__device__ __nv_bfloat16 g_Bww[(size_t)1024 * KXW];      // [jcat,768] = [wh|wh|wl]
__device__ float         g_xpr[(size_t)NP_M * 1024];     // fp32: 0:512 x@Wn, 512:1024 x@Wr
__device__ int8_t        g_xq[(size_t)1024 * NP_K2];     // [jcat,n]: rows 0:512 dh, 512:1024 dl
__device__ int8_t        g_Hs8[(size_t)NP_M * MP_K2];    // [n,m] s8 0/1
__device__ int8_t        g_Hts8[(size_t)MP_M * NP_K2];   // [m,n] s8 0/1 (transpose)
__device__ float         g_EFt[(size_t)512 * MP_K2];     // edge_feat transposed [j,m] fp32
__device__ int8_t        g_Eq[(size_t)1024 * MP_K2];     // [jcat,m]: rows 0:512 dh, 512:1024 dl
__device__ int           g_D2i[(size_t)4 * MP_M * 1024]; // 4 K-split slabs [m,jcat] s32
__device__ int           g_D3i[(size_t)NP_M * 1024];     // [n,jcat] s32
__device__ float         g_dv_sum[N_NODES];
__device__ float         g_de_sum[MP_M];
__device__ float         g_inv_dv[N_NODES];
__device__ float         g_inv_de[MP_M];
__device__ unsigned      g_absmax;

// ============================ helpers ============================
__device__ __forceinline__ uint32_t smem_u32(const void* p) {
    uint32_t a;
    asm("{ .reg .u64 t; cvta.to.shared.u64 t, %1; cvt.u32.u64 %0, t; }" : "=r"(a) : "l"(p));
    return a;
}
__device__ __forceinline__ void cp16(uint32_t dst, const void* src) {
    asm volatile("cp.async.cg.shared.global [%0], [%1], 16;" :: "r"(dst), "l"(src));
}
#define CP_COMMIT() asm volatile("cp.async.commit_group;" ::: "memory")
#define CP_WAIT(n)  asm volatile("cp.async.wait_group %0;" :: "n"(n) : "memory")

__device__ __forceinline__ void ldsm4(uint32_t* r, uint32_t addr) {
    asm volatile("ldmatrix.sync.aligned.m8n8.x4.shared.b16 {%0,%1,%2,%3}, [%4];"
        : "=r"(r[0]), "=r"(r[1]), "=r"(r[2]), "=r"(r[3]) : "r"(addr));
}
__device__ __forceinline__ void mma16816(float* c, const uint32_t* a,
                                         uint32_t b0, uint32_t b1) {
    asm volatile(
        "mma.sync.aligned.m16n8k16.row.col.f32.bf16.bf16.f32 "
        "{%0,%1,%2,%3}, {%4,%5,%6,%7}, {%8,%9}, {%0,%1,%2,%3};"
        : "+f"(c[0]), "+f"(c[1]), "+f"(c[2]), "+f"(c[3])
        : "r"(a[0]), "r"(a[1]), "r"(a[2]), "r"(a[3]), "r"(b0), "r"(b1));
}
__device__ __forceinline__ void imma16832(int* c, const uint32_t* a,
                                          uint32_t b0, uint32_t b1) {
    asm volatile(
        "mma.sync.aligned.m16n8k32.row.col.s32.s8.s8.s32 "
        "{%0,%1,%2,%3}, {%4,%5,%6,%7}, {%8,%9}, {%0,%1,%2,%3};"
        : "+r"(c[0]), "+r"(c[1]), "+r"(c[2]), "+r"(c[3])
        : "r"(a[0]), "r"(a[1]), "r"(a[2]), "r"(a[3]), "r"(b0), "r"(b1));
}

// ====================== shared GEMM tiling constants ======================
// BM=128, BN=128, 256 threads (8 warps, 2m x 4n -> 64x32 warp tile),
// 3-stage cp.async, double-buffered ldmatrix fragments, 2 CTAs/SM.
// Rows are 128 BYTES of K data (+16B pad): bf16 -> BK=64 elems, s8 -> BK=128.
#define STAGES 3
#define PITCH 144
#define ST_A (128 * PITCH)
#define ST_B (128 * PITCH)
#define ST_SZ (ST_A + ST_B)          // 36864
#define SMEM_MMA (ST_SZ * STAGES)    // 110592 -> 2 CTAs/SM

// ============================ bf16 GEMM (GEMM1) =============================
__global__ __launch_bounds__(256, 2) void mma_bf16_kernel(
    const __nv_bfloat16* __restrict__ A, const __nv_bfloat16* __restrict__ B,
    float* __restrict__ D, int ldab, int nch)
{
    extern __shared__ char dynsmem[];
    const uint32_t sb = smem_u32(dynsmem);
    const int tid = threadIdx.x;
    const int lane = tid & 31, wid = tid >> 5;
    const int wm = wid & 1, wn = wid >> 1;
    const int row0 = blockIdx.x * 128;
    const int col0 = blockIdx.y * 128;

    const __nv_bfloat16* Ab = A + (size_t)row0 * ldab;
    const __nv_bfloat16* Bb = B + (size_t)col0 * ldab;

    const int ra = (lane & 7) + ((lane >> 3) & 1) * 8;
    const int rb = (lane & 7) + (lane >> 4) * 8;
    const uint32_t aoff = (wm * 64 + ra) * PITCH + (lane >> 4) * 16;
    const uint32_t boff = (wn * 32 + rb) * PITCH + ((lane >> 3) & 1) * 16;
    const int lr = tid >> 3, ls = tid & 7;

    float acc[4][4][4];
#pragma unroll
    for (int i = 0; i < 4; i++)
#pragma unroll
        for (int j = 0; j < 4; j++)
#pragma unroll
            for (int k = 0; k < 4; k++) acc[i][j][k] = 0.f;

    auto issue_load = [&](int buf, int chunk) {
        const uint32_t sa = sb + buf * ST_SZ;
        const uint32_t sB = sa + ST_A;
        const __nv_bfloat16* Ak = Ab + (size_t)chunk * 64;
        const __nv_bfloat16* Bk = Bb + (size_t)chunk * 64;
#pragma unroll
        for (int i = 0; i < 4; i++) {
            int r = lr + i * 32;
            cp16(sa + r * PITCH + ls * 16, Ak + (size_t)r * ldab + ls * 8);
            cp16(sB + r * PITCH + ls * 16, Bk + (size_t)r * ldab + ls * 8);
        }
    };

    issue_load(0, 0); CP_COMMIT();
    if (nch > 1) issue_load(1, 1);
    CP_COMMIT();

    for (int it = 0; it < nch; it++) {
        CP_WAIT(1);
        __syncthreads();
        const uint32_t sa = sb + (it % STAGES) * ST_SZ;
        const uint32_t sB = sa + ST_A;

        uint32_t afr[2][4][4], bfr[2][2][4];
#pragma unroll
        for (int mb = 0; mb < 4; mb++) ldsm4(afr[0][mb], sa + aoff + mb * 16 * PITCH);
#pragma unroll
        for (int np = 0; np < 2; np++) ldsm4(bfr[0][np], sB + boff + np * 16 * PITCH);

#pragma unroll
        for (int ks = 0; ks < 4; ks++) {
            const int cur = ks & 1, nxt = cur ^ 1;
            if (ks < 3) {
                const uint32_t ko = (ks + 1) * 32;
#pragma unroll
                for (int mb = 0; mb < 4; mb++)
                    ldsm4(afr[nxt][mb], sa + aoff + mb * 16 * PITCH + ko);
#pragma unroll
                for (int np = 0; np < 2; np++)
                    ldsm4(bfr[nxt][np], sB + boff + np * 16 * PITCH + ko);
            }
#pragma unroll
            for (int mb = 0; mb < 4; mb++)
#pragma unroll
                for (int np = 0; np < 2; np++) {
                    mma16816(acc[mb][np * 2], afr[cur][mb], bfr[cur][np][0], bfr[cur][np][1]);
                    mma16816(acc[mb][np * 2 + 1], afr[cur][mb], bfr[cur][np][2], bfr[cur][np][3]);
                }
        }
        __syncthreads();
        if (it + 2 < nch) issue_load((it + 2) % STAGES, it + 2);
        CP_COMMIT();
    }

    const int rbase = row0 + wm * 64 + (lane >> 2);
    const int cbase = col0 + wn * 32 + (lane & 3) * 2;
#pragma unroll
    for (int mb = 0; mb < 4; mb++)
#pragma unroll
        for (int nb = 0; nb < 4; nb++) {
            const int r = rbase + mb * 16;
            const int c = cbase + nb * 8;
            *(float2*)&D[(size_t)r * 1024 + c] = make_float2(acc[mb][nb][0], acc[mb][nb][1]);
            *(float2*)&D[(size_t)(r + 8) * 1024 + c] = make_float2(acc[mb][nb][2], acc[mb][nb][3]);
        }
}

// ============================ s8 GEMM (GEMM2/3) =============================
// Same tiling; rows are 128 s8 K-bytes. ldab in bytes. s32 output ld=1024.
__global__ __launch_bounds__(256, 2) void mma_s8_kernel(
    const int8_t* __restrict__ A, const int8_t* __restrict__ B,
    int* __restrict__ D, int ldab,
    int total_chunks, int chunks_per_z, long long dzstride)
{
    extern __shared__ char dynsmem[];
    const uint32_t sb = smem_u32(dynsmem);
    const int tid = threadIdx.x;
    const int lane = tid & 31, wid = tid >> 5;
    const int wm = wid & 1, wn = wid >> 1;
    const int row0 = blockIdx.x * 128;
    const int col0 = blockIdx.y * 128;

    const int kc0 = blockIdx.z * chunks_per_z;
    int nch = total_chunks - kc0; if (nch > chunks_per_z) nch = chunks_per_z;
    D += (long long)blockIdx.z * dzstride;

    const int8_t* Ab = A + (size_t)row0 * ldab + (size_t)kc0 * 128;
    const int8_t* Bb = B + (size_t)col0 * ldab + (size_t)kc0 * 128;

    const int ra = (lane & 7) + ((lane >> 3) & 1) * 8;
    const int rb = (lane & 7) + (lane >> 4) * 8;
    const uint32_t aoff = (wm * 64 + ra) * PITCH + (lane >> 4) * 16;
    const uint32_t boff = (wn * 32 + rb) * PITCH + ((lane >> 3) & 1) * 16;
    const int lr = tid >> 3, ls = tid & 7;

    int acc[4][4][4];
#pragma unroll
    for (int i = 0; i < 4; i++)
#pragma unroll
        for (int j = 0; j < 4; j++)
#pragma unroll
            for (int k = 0; k < 4; k++) acc[i][j][k] = 0;

    auto issue_load = [&](int buf, int chunk) {
        const uint32_t sa = sb + buf * ST_SZ;
        const uint32_t sB = sa + ST_A;
        const int8_t* Ak = Ab + (size_t)chunk * 128;
        const int8_t* Bk = Bb + (size_t)chunk * 128;
#pragma unroll
        for (int i = 0; i < 4; i++) {
            int r = lr + i * 32;
            cp16(sa + r * PITCH + ls * 16, Ak + (size_t)r * ldab + ls * 16);
            cp16(sB + r * PITCH + ls * 16, Bk + (size_t)r * ldab + ls * 16);
        }
    };

    issue_load(0, 0); CP_COMMIT();
    if (nch > 1) issue_load(1, 1);
    CP_COMMIT();

    for (int it = 0; it < nch; it++) {
        CP_WAIT(1);
        __syncthreads();
        const uint32_t sa = sb + (it % STAGES) * ST_SZ;
        const uint32_t sB = sa + ST_A;

        uint32_t afr[2][4][4], bfr[2][2][4];
#pragma unroll
        for (int mb = 0; mb < 4; mb++) ldsm4(afr[0][mb], sa + aoff + mb * 16 * PITCH);
#pragma unroll
        for (int np = 0; np < 2; np++) ldsm4(bfr[0][np], sB + boff + np * 16 * PITCH);

#pragma unroll
        for (int ks = 0; ks < 4; ks++) {   // 4 x k32 bytes = 128-byte chunk
            const int cur = ks & 1, nxt = cur ^ 1;
            if (ks < 3) {
                const uint32_t ko = (ks + 1) * 32;
#pragma unroll
                for (int mb = 0; mb < 4; mb++)
                    ldsm4(afr[nxt][mb], sa + aoff + mb * 16 * PITCH + ko);
#pragma unroll
                for (int np = 0; np < 2; np++)
                    ldsm4(bfr[nxt][np], sB + boff + np * 16 * PITCH + ko);
            }
#pragma unroll
            for (int mb = 0; mb < 4; mb++)
#pragma unroll
                for (int np = 0; np < 2; np++) {
                    imma16832(acc[mb][np * 2], afr[cur][mb], bfr[cur][np][0], bfr[cur][np][1]);
                    imma16832(acc[mb][np * 2 + 1], afr[cur][mb], bfr[cur][np][2], bfr[cur][np][3]);
                }
        }
        __syncthreads();
        if (it + 2 < nch) issue_load((it + 2) % STAGES, it + 2);
        CP_COMMIT();
    }

    const int rbase = row0 + wm * 64 + (lane >> 2);
    const int cbase = col0 + wn * 32 + (lane & 3) * 2;
#pragma unroll
    for (int mb = 0; mb < 4; mb++)
#pragma unroll
        for (int nb = 0; nb < 4; nb++) {
            const int r = rbase + mb * 16;
            const int c = cbase + nb * 8;
            *(int2*)&D[(size_t)r * 1024 + c] = make_int2(acc[mb][nb][0], acc[mb][nb][1]);
            *(int2*)&D[(size_t)(r + 8) * 1024 + c] = make_int2(acc[mb][nb][2], acc[mb][nb][3]);
        }
}

// ===================== conversion / epilogue kernels =====================
__global__ void zero_sums_kernel()
{
    int i = blockIdx.x * blockDim.x + threadIdx.x;
    if (i < N_NODES) g_dv_sum[i] = 0.f;
    if (i < MP_M) g_de_sum[i] = 0.f;
    if (i == 0) g_absmax = 0u;
}

// H -> Hs8 [n,m], Hts8 [m,n], plus degree partial sums. 32x32 tiles.
__global__ __launch_bounds__(256) void convH_kernel(const float* __restrict__ H)
{
    __shared__ float tile[32][33];
    __shared__ float colpart[8][32];
    const int tx = threadIdx.x, ty = threadIdx.y;
    const int m0 = blockIdx.x * 32, n0 = blockIdx.y * 32;
    const int m = m0 + tx;
    float v[4];
#pragma unroll
    for (int r = 0; r < 4; r++) {
        int n = n0 + ty * 4 + r;
        float val = (m < M_EDGES) ? H[(size_t)n * M_EDGES + m] : 0.f;
        v[r] = val;
        tile[ty * 4 + r][tx] = val;
        if (m < M_EDGES)
            g_Hs8[(size_t)n * MP_K2 + m] = (int8_t)val;
    }
#pragma unroll
    for (int r = 0; r < 4; r++) {
        float s = v[r];
#pragma unroll
        for (int o = 16; o > 0; o >>= 1) s += __shfl_xor_sync(0xffffffffu, s, o);
        if (tx == 0) atomicAdd(&g_dv_sum[n0 + ty * 4 + r], s);
    }
    colpart[ty][tx] = v[0] + v[1] + v[2] + v[3];
    __syncthreads();
    if (ty == 0 && m < M_EDGES) {
        float s = 0.f;
#pragma unroll
        for (int w = 0; w < 8; w++) s += colpart[w][tx];
        atomicAdd(&g_de_sum[m], s);
    }
#pragma unroll
    for (int r = 0; r < 4; r++) {
        int ml = ty * 4 + r;
        if (m0 + ml < M_EDGES)
            g_Hts8[(size_t)(m0 + ml) * NP_K2 + n0 + tx] = (int8_t)tile[tx][ml];
    }
}

__global__ void deg_fin_kernel()
{
    int i = blockIdx.x * blockDim.x + threadIdx.x;
    if (i < N_NODES) g_inv_dv[i] = 1.0f / fmaxf(g_dv_sum[i], 1.0f);
    if (i < M_EDGES) g_inv_de[i] = 1.0f / fmaxf(g_de_sum[i], 1.0f);
}

// x [n,256] -> Axx [n,768] = [xh | xl | xh]
__global__ __launch_bounds__(256) void convX_kernel(const float* __restrict__ x)
{
    const int n = blockIdx.x, k = threadIdx.x;
    float v = x[(size_t)n * DIN + k];
    __nv_bfloat16 hi = __float2bfloat16(v);
    __nv_bfloat16 lo = __float2bfloat16(v - __bfloat162float(hi));
    __nv_bfloat16* row = g_Axx + (size_t)n * KXW;
    row[k] = hi; row[256 + k] = lo; row[512 + k] = hi;
}

// Wn,Wr [256,512] -> Bww [jcat,768] = [wh | wh | wl]
__global__ __launch_bounds__(256) void convW_kernel(
    const float* __restrict__ Wn, const float* __restrict__ Wr)
{
    const int j = blockIdx.x, k = threadIdx.x;
    float v = (j < DOUTD) ? Wn[(size_t)k * DOUTD + j]
                          : Wr[(size_t)k * DOUTD + (j - DOUTD)];
    __nv_bfloat16 hi = __float2bfloat16(v);
    __nv_bfloat16 lo = __float2bfloat16(v - __bfloat162float(hi));
    __nv_bfloat16* row = g_Bww + (size_t)j * KXW;
    row[k] = hi; row[256 + k] = hi; row[512 + k] = lo;
}

__device__ __forceinline__ void quant2(float v, float scale_inv, int8_t& dh, int8_t& dl)
{
    int q = __float2int_rn(v * scale_inv);
    q = max(-QCLAMP - 1, min(QCLAMP, q));
    int h = (q + 64) >> 7;          // round-to-nearest digit split
    dh = (int8_t)h;
    dl = (int8_t)(q - (h << 7));
}

// g_xpr cols 0:512 -> g_xq digit rows (tiled transpose + quantize)
__global__ __launch_bounds__(256) void convXpr_kernel()
{
    __shared__ float tile[32][33];
    const int tx = threadIdx.x, ty = threadIdx.y;
    const int n0 = blockIdx.x * 32, j0 = blockIdx.y * 32;
#pragma unroll
    for (int r = 0; r < 4; r++) {
        int nl = ty * 4 + r;
        tile[nl][tx] = g_xpr[(size_t)(n0 + nl) * 1024 + j0 + tx];
    }
    __syncthreads();
#pragma unroll
    for (int r = 0; r < 4; r++) {
        int jl = ty * 4 + r;
        int8_t dh, dl;
        quant2(tile[tx][jl], SX_INV, dh, dl);
        g_xq[(size_t)(j0 + jl) * NP_K2 + n0 + tx] = dh;
        g_xq[(size_t)(512 + j0 + jl) * NP_K2 + n0 + tx] = dl;
    }
}

// D2i slabs -> edge_feat fp32 transposed [j,m] + absmax
__global__ __launch_bounds__(256) void ep2_kernel()
{
    __shared__ float tile[32][33];
    const int tx = threadIdx.x, ty = threadIdx.y;
    const int m0 = blockIdx.x * 32, j0 = blockIdx.y * 32;
    float lmax = 0.f;
#pragma unroll
    for (int r = 0; r < 4; r++) {
        int ml = ty * 4 + r;
        size_t base = (size_t)(m0 + ml) * 1024;
        int j = j0 + tx;
        int q = 0;
#pragma unroll
        for (int z = 0; z < 4; z++) {
            const int* Dz = g_D2i + (size_t)z * MP_M * 1024;
            q += Dz[base + j] * 128 + Dz[base + 512 + j];
        }
        float e = (float)q * SX_VAL * g_inv_de[m0 + ml];
        tile[ml][tx] = e;
        lmax = fmaxf(lmax, fabsf(e));
    }
#pragma unroll
    for (int o = 16; o > 0; o >>= 1)
        lmax = fmaxf(lmax, __shfl_xor_sync(0xffffffffu, lmax, o));
    if (tx == 0) atomicMax(&g_absmax, __float_as_uint(lmax));
    __syncthreads();
#pragma unroll
    for (int r = 0; r < 4; r++) {
        int jl = ty * 4 + r;
        g_EFt[(size_t)(j0 + jl) * MP_K2 + m0 + tx] = tile[tx][jl];
    }
}

// digitize edge_feat with dynamic scale
__global__ __launch_bounds__(256) void digitizeE_kernel()
{
    const size_t idx = (size_t)blockIdx.x * 256 + threadIdx.x;
    if (idx >= (size_t)512 * MP_K2) return;
    const float amax = __uint_as_float(g_absmax);
    const float sinv = (amax > 0.f) ? (float)QCLAMP / amax : 0.f;
    int8_t dh, dl;
    quant2(g_EFt[idx], sinv, dh, dl);
    const size_t j = idx / MP_K2, m = idx % MP_K2;
    g_Eq[j * MP_K2 + m] = dh;
    g_Eq[(512 + j) * MP_K2 + m] = dl;
}

// final: fold D3i digits, /d_v, +residual, LayerNorm -> out
__device__ __forceinline__ float block_sum_256(float v, float* red)
{
#pragma unroll
    for (int o = 16; o > 0; o >>= 1) v += __shfl_xor_sync(0xffffffffu, v, o);
    int w = threadIdx.x >> 5;
    if ((threadIdx.x & 31) == 0) red[w] = v;
    __syncthreads();
    if (threadIdx.x < 32) {
        float r = (threadIdx.x < 8) ? red[threadIdx.x] : 0.0f;
#pragma unroll
        for (int o = 4; o > 0; o >>= 1) r += __shfl_xor_sync(0xffffffffu, r, o);
        if (threadIdx.x == 0) red[0] = r;
    }
    __syncthreads();
    float res = red[0];
    __syncthreads();
    return res;
}

__global__ __launch_bounds__(256) void ln_kernel(
    const float* __restrict__ gamma, const float* __restrict__ beta,
    float* __restrict__ out)
{
    __shared__ float red[8];
    const int n = blockIdx.x, t = threadIdx.x;
    const float inv_dv = g_inv_dv[n];
    const float amax = __uint_as_float(g_absmax);
    const float S3 = (amax > 0.f) ? amax / (float)QCLAMP : 0.f;
    const size_t base = (size_t)n * 1024;
    int2 a = *(const int2*)&g_D3i[base + t * 2];
    int2 b = *(const int2*)&g_D3i[base + 512 + t * 2];
    float2 r = *(const float2*)&g_xpr[base + 512 + t * 2];
    float hx = (float)(a.x * 128 + b.x) * S3 * inv_dv + r.x;
    float hy = (float)(a.y * 128 + b.y) * S3 * inv_dv + r.y;
    float mu = block_sum_256(hx + hy, red) * (1.0f / DOUTD);
    float dx = hx - mu, dy = hy - mu;
    float var = block_sum_256(dx * dx + dy * dy, red) * (1.0f / DOUTD);
    float rs = rsqrtf(var + 1e-5f);
    float2 g = *(const float2*)&gamma[t * 2];
    float2 be = *(const float2*)&beta[t * 2];
    float* o = out + (size_t)n * DOUTD;
    o[t * 2 + 0] = dx * rs * g.x + be.x;
    o[t * 2 + 1] = dy * rs * g.y + be.y;
}

// ============================== launch ==============================
extern "C" void kernel_launch(void* const* d_in, const int* in_sizes, int n_in,
                              void* d_out, int out_size)
{
    const float* x     = (const float*)d_in[0];
    const float* H     = (const float*)d_in[1];
    const float* Wn    = (const float*)d_in[2];
    const float* Wr    = (const float*)d_in[3];
    const float* gamma = (const float*)d_in[4];
    const float* beta  = (const float*)d_in[5];
    float* out = (float*)d_out;

    cudaFuncSetAttribute(mma_bf16_kernel, cudaFuncAttributeMaxDynamicSharedMemorySize, SMEM_MMA);
    cudaFuncSetAttribute(mma_s8_kernel, cudaFuncAttributeMaxDynamicSharedMemorySize, SMEM_MMA);

    __nv_bfloat16 *Axx, *Bww;
    int8_t *xq, *Hs8, *Hts8, *Eq;
    float *xpr;
    int *D2i, *D3i;
    cudaGetSymbolAddress((void**)&Axx, g_Axx);
    cudaGetSymbolAddress((void**)&Bww, g_Bww);
    cudaGetSymbolAddress((void**)&xpr, g_xpr);
    cudaGetSymbolAddress((void**)&xq, g_xq);
    cudaGetSymbolAddress((void**)&Hs8, g_Hs8);
    cudaGetSymbolAddress((void**)&Hts8, g_Hts8);
    cudaGetSymbolAddress((void**)&Eq, g_Eq);
    cudaGetSymbolAddress((void**)&D2i, g_D2i);
    cudaGetSymbolAddress((void**)&D3i, g_D3i);

    zero_sums_kernel<<<79, 256>>>();
    convX_kernel<<<N_NODES, 256>>>(x);
    convW_kernel<<<1024, 256>>>(Wn, Wr);

    // GEMM1 (bf16): g_xpr[n,1024] = Axx @ Bww^T   (K=768 -> 12 chunks)
    mma_bf16_kernel<<<dim3(157, 8), 256, SMEM_MMA>>>(Axx, Bww, xpr, KXW, 12);

    convH_kernel<<<dim3(157, 625), dim3(32, 8)>>>(H);
    deg_fin_kernel<<<79, 256>>>();
    convXpr_kernel<<<dim3(625, 16), dim3(32, 8)>>>();

    // GEMM2 (s8): D2i[z][m,1024] = Hts8 @ xq^T   (157 chunks, K-split 4)
    mma_s8_kernel<<<dim3(40, 8, 4), 256, SMEM_MMA>>>(Hts8, xq, D2i, NP_K2, 157, 40,
                                                     (long long)MP_M * 1024);

    ep2_kernel<<<dim3(160, 16), dim3(32, 8)>>>();
    digitizeE_kernel<<<(512 * MP_K2 + 255) / 256, 256>>>();

    // GEMM3 (s8): D3i[n,1024] = Hs8 @ Eq^T       (40 chunks)
    mma_s8_kernel<<<dim3(157, 8, 1), 256, SMEM_MMA>>>(Hs8, Eq, D3i, MP_K2, 40, 40, 0);

    ln_kernel<<<N_NODES, 256>>>(gamma, beta, out);
}